// round 2
// baseline (speedup 1.0000x reference)
#include <cuda_runtime.h>
#include <cstdint>
#include <cstddef>

// ---------------- problem constants ----------------
#define Bx 2
#define Sx 2048
#define Hx 1024
#define NH 16
#define HD 64
#define BSx (Bx*Sx)          // 4096
#define TOPK 128
#define LN_EPS 1e-5f

// ---------------- scratch (device globals; no allocation) ----------------
__device__ float    g_Q[BSx*Hx];
__device__ float    g_K[BSx*Hx];
__device__ float    g_V[BSx*Hx];
__device__ float    g_ctx[BSx*Hx];        // [B, nh, S, hd] = same element count
__device__ float    g_z[32*16*2048];      // [n=32][h2=16][m=2048]
__device__ unsigned g_thr[32*16];
__device__ float    g_y[BSx*Hx];
__device__ float    g_vw[NH*HD];
__device__ float    g_ow[NH*HD];

// ---------------- order-preserving float->uint ----------------
__device__ __forceinline__ unsigned f2ord(float f) {
    unsigned u = __float_as_uint(f);
    return (u >> 31) ? ~u : (u | 0x80000000u);
}

// ---------------- SGEMM (NT): C[M,N] = A[M,K] * B[N,K]^T, all row-major ----
// 128x128 tile, BK=16, 256 threads, 8x8 micro-tile. M%128==0, N%128==0, K%16==0.
#define BM 128
#define BN 128
#define BKK 16

__global__ __launch_bounds__(256) void sgemm_nt(const float* __restrict__ A,
                                                const float* __restrict__ B,
                                                float* __restrict__ C,
                                                int M, int N, int K) {
    __shared__ float As[BKK][BM + 4];
    __shared__ float Bs[BKK][BN + 4];
    const int tid = threadIdx.x;
    const int tx = tid & 15, ty = tid >> 4;
    const int m0 = blockIdx.y * BM, n0 = blockIdx.x * BN;

    float acc[8][8];
#pragma unroll
    for (int i = 0; i < 8; i++)
#pragma unroll
        for (int j = 0; j < 8; j++) acc[i][j] = 0.f;

    for (int k0 = 0; k0 < K; k0 += BKK) {
#pragma unroll
        for (int it = 0; it < 2; it++) {
            int idx = tid + it * 256;            // 0..511
            int row = idx >> 2;
            int c4  = (idx & 3) * 4;
            float4 va = *(const float4*)(A + (size_t)(m0 + row) * K + k0 + c4);
            As[c4 + 0][row] = va.x; As[c4 + 1][row] = va.y;
            As[c4 + 2][row] = va.z; As[c4 + 3][row] = va.w;
            float4 vb = *(const float4*)(B + (size_t)(n0 + row) * K + k0 + c4);
            Bs[c4 + 0][row] = vb.x; Bs[c4 + 1][row] = vb.y;
            Bs[c4 + 2][row] = vb.z; Bs[c4 + 3][row] = vb.w;
        }
        __syncthreads();
#pragma unroll
        for (int kk = 0; kk < BKK; kk++) {
            float4 a0 = *(const float4*)&As[kk][ty * 8];
            float4 a1 = *(const float4*)&As[kk][ty * 8 + 4];
            float4 b0 = *(const float4*)&Bs[kk][tx * 8];
            float4 b1 = *(const float4*)&Bs[kk][tx * 8 + 4];
            float a[8] = {a0.x, a0.y, a0.z, a0.w, a1.x, a1.y, a1.z, a1.w};
            float b[8] = {b0.x, b0.y, b0.z, b0.w, b1.x, b1.y, b1.z, b1.w};
#pragma unroll
            for (int i = 0; i < 8; i++)
#pragma unroll
                for (int j = 0; j < 8; j++) acc[i][j] += a[i] * b[j];
        }
        __syncthreads();
    }
#pragma unroll
    for (int i = 0; i < 8; i++) {
        size_t off = (size_t)(m0 + ty * 8 + i) * N + n0 + tx * 8;
        float4 o0 = {acc[i][0], acc[i][1], acc[i][2], acc[i][3]};
        float4 o1 = {acc[i][4], acc[i][5], acc[i][6], acc[i][7]};
        *(float4*)(C + off)     = o0;
        *(float4*)(C + off + 4) = o1;
    }
}

// ---------------- per-head LayerNorm on Q and K (in place) ------------------
// one warp per 64-float head-row; Q rows [0,65536), K rows [65536,131072)
__global__ __launch_bounds__(256) void ln_kernel(float* __restrict__ Q,
                                                 float* __restrict__ Kp,
                                                 const float* __restrict__ qw,
                                                 const float* __restrict__ qb,
                                                 const float* __restrict__ kw,
                                                 const float* __restrict__ kb) {
    int warp = threadIdx.x >> 5, lane = threadIdx.x & 31;
    int rid = blockIdx.x * 8 + warp;
    float* base;
    const float *w, *bb;
    if (rid < BSx * NH) { base = Q + (size_t)rid * 64; w = qw; bb = qb; }
    else { base = Kp + (size_t)(rid - BSx * NH) * 64; w = kw; bb = kb; }
    float x0 = base[lane], x1 = base[lane + 32];
    float sum = x0 + x1;
#pragma unroll
    for (int off = 16; off; off >>= 1) sum += __shfl_xor_sync(~0u, sum, off);
    float mu = sum * (1.f / 64.f);
    float d0 = x0 - mu, d1 = x1 - mu;
    float vs = d0 * d0 + d1 * d1;
#pragma unroll
    for (int off = 16; off; off >>= 1) vs += __shfl_xor_sync(~0u, vs, off);
    float rs = rsqrtf(vs * (1.f / 64.f) + LN_EPS);
    base[lane]      = d0 * rs * w[lane]      + bb[lane];
    base[lane + 32] = d1 * rs * w[lane + 32] + bb[lane + 32];
}

// ---------------- flash attention, fp32 -------------------------------------
// grid (S/64, nh, B), block 256 (16x16). 64 queries, 32-key tiles.
// thread (ty,tx): score rows ty*4+i, score cols tx*2+j; ctx cols tx*4+j.
__global__ __launch_bounds__(256) void attn_kernel(const float* __restrict__ Qg,
                                                   const float* __restrict__ Kg,
                                                   const float* __restrict__ Vg) {
    __shared__ float Qs[64][68];
    __shared__ float Ks[32][68];
    __shared__ float Vs[32][68];
    __shared__ float Ps[64][33];

    const int qt = blockIdx.x, h = blockIdx.y, b = blockIdx.z;
    const int tid = threadIdx.x;
    const int tx = tid & 15, ty = tid >> 4;
    const int q0 = qt * 64;
    const float scale = 0.125f;   // 1/sqrt(64)

    const float* qb_ = Qg + (size_t)(b * Sx + q0) * Hx + h * HD;
#pragma unroll
    for (int it = 0; it < 4; it++) {
        int idx = tid + it * 256;           // 0..1023 = 64 rows x 16 float4
        int r = idx >> 4, c4 = (idx & 15) * 4;
        float4 v = *(const float4*)(qb_ + (size_t)r * Hx + c4);
        v.x *= scale; v.y *= scale; v.z *= scale; v.w *= scale;
        *(float4*)&Qs[r][c4] = v;
    }

    float m_run[4], l_run[4], acc[4][4];
#pragma unroll
    for (int i = 0; i < 4; i++) {
        m_run[i] = -1e30f; l_run[i] = 0.f;
#pragma unroll
        for (int j = 0; j < 4; j++) acc[i][j] = 0.f;
    }

    for (int kt = 0; kt < Sx / 32; kt++) {
        __syncthreads();
        const float* kb_ = Kg + (size_t)(b * Sx + kt * 32) * Hx + h * HD;
        const float* vb_ = Vg + (size_t)(b * Sx + kt * 32) * Hx + h * HD;
#pragma unroll
        for (int it = 0; it < 2; it++) {
            int idx = tid + it * 256;       // 0..511 = 32 rows x 16 float4
            int r = idx >> 4, c4 = (idx & 15) * 4;
            *(float4*)&Ks[r][c4] = *(const float4*)(kb_ + (size_t)r * Hx + c4);
            *(float4*)&Vs[r][c4] = *(const float4*)(vb_ + (size_t)r * Hx + c4);
        }
        __syncthreads();

        // GEMM1: s[i][j] = Q[row] . K[col]
        float s[4][2];
#pragma unroll
        for (int i = 0; i < 4; i++) { s[i][0] = 0.f; s[i][1] = 0.f; }
#pragma unroll
        for (int kk = 0; kk < 64; kk += 4) {
            float4 b0 = *(const float4*)&Ks[tx * 2 + 0][kk];
            float4 b1 = *(const float4*)&Ks[tx * 2 + 1][kk];
#pragma unroll
            for (int i = 0; i < 4; i++) {
                float4 a = *(const float4*)&Qs[ty * 4 + i][kk];
                s[i][0] += a.x * b0.x + a.y * b0.y + a.z * b0.z + a.w * b0.w;
                s[i][1] += a.x * b1.x + a.y * b1.y + a.z * b1.z + a.w * b1.w;
            }
        }

        // online softmax (row reduces across the 16-lane tx group)
#pragma unroll
        for (int i = 0; i < 4; i++) {
            float tmax = fmaxf(s[i][0], s[i][1]);
#pragma unroll
            for (int off = 8; off; off >>= 1)
                tmax = fmaxf(tmax, __shfl_xor_sync(~0u, tmax, off, 16));
            float mnew = fmaxf(m_run[i], tmax);
            float p0 = __expf(s[i][0] - mnew);
            float p1 = __expf(s[i][1] - mnew);
            float lsum = p0 + p1;
#pragma unroll
            for (int off = 8; off; off >>= 1)
                lsum += __shfl_xor_sync(~0u, lsum, off, 16);
            float alpha = __expf(m_run[i] - mnew);
            l_run[i] = l_run[i] * alpha + lsum;
            m_run[i] = mnew;
#pragma unroll
            for (int j = 0; j < 4; j++) acc[i][j] *= alpha;
            Ps[ty * 4 + i][tx * 2 + 0] = p0;
            Ps[ty * 4 + i][tx * 2 + 1] = p1;
        }
        __syncwarp();

        // GEMM2: acc[i][j] += sum_c P[row][c] * V[c][col]
#pragma unroll
        for (int c = 0; c < 32; c++) {
            float4 bv = *(const float4*)&Vs[c][tx * 4];
#pragma unroll
            for (int i = 0; i < 4; i++) {
                float a = Ps[ty * 4 + i][c];
                acc[i][0] += a * bv.x; acc[i][1] += a * bv.y;
                acc[i][2] += a * bv.z; acc[i][3] += a * bv.w;
            }
        }
    }

    float* ob = g_ctx + ((size_t)(b * NH + h) * Sx + q0) * HD;
#pragma unroll
    for (int i = 0; i < 4; i++) {
        float inv = 1.f / l_run[i];
        float4 o = {acc[i][0] * inv, acc[i][1] * inv, acc[i][2] * inv, acc[i][3] * inv};
        *(float4*)(ob + (size_t)(ty * 4 + i) * HD + tx * 4) = o;
    }
}

// ---------------- z = mixed-context . vw  ------------------------------------
// grid (16 m-chunks, 32 n), block 256.
__global__ __launch_bounds__(256) void z_kernel() {
    __shared__ float cs[128][65];
    __shared__ float vws[NH * HD];
    int t = threadIdx.x;
    int n = blockIdx.y, m0 = blockIdx.x * 128;
    for (int i = t; i < NH * HD; i += 256) vws[i] = g_vw[i];
    int b = n >> 4, hi = n & 15;
#pragma unroll 8
    for (int it = 0; it < 32; it++) {
        int f = t + it * 256;          // 0..8191
        int j = f >> 6, d = f & 63;
        int m = m0 + j;
        int t2 = hi * Sx + m;
        int s = t2 >> 4, hh = t2 & 15;
        cs[j][d] = g_ctx[((size_t)(b * NH + hh) * Sx + s) * HD + d];
    }
    __syncthreads();
#pragma unroll 1
    for (int p = 0; p < 8; p++) {
        int h2 = p * 2 + (t >> 7);
        int ml = t & 127;
        const float* vr = &vws[h2 * HD];
        float a = 0.f;
#pragma unroll
        for (int d = 0; d < 64; d++) a += cs[ml][d] * vr[d];
        g_z[((size_t)n * 16 + h2) * Sx + m0 + ml] = a;
    }
}

// ---------------- top-128 threshold per row (binary search on ordered bits) --
__global__ __launch_bounds__(256) void topk_kernel() {
    int row = blockIdx.x, t = threadIdx.x;
    const float* zr = g_z + (size_t)row * Sx;
    unsigned v[8];
#pragma unroll
    for (int i = 0; i < 8; i++) v[i] = f2ord(zr[t + i * 256]);
    __shared__ int scnt;
    unsigned lo = 0u, hi = 0xFFFFFFFFu;
    while (lo < hi) {
        unsigned mid = lo + ((hi - lo) >> 1);
        int c = 0;
#pragma unroll
        for (int i = 0; i < 8; i++) c += (v[i] > mid);
#pragma unroll
        for (int off = 16; off; off >>= 1) c += __shfl_xor_sync(~0u, c, off);
        __syncthreads();
        if (t == 0) scnt = 0;
        __syncthreads();
        if ((t & 31) == 0) atomicAdd(&scnt, c);
        __syncthreads();
        int tot = scnt;
        if (tot >= TOPK) lo = mid + 1; else hi = mid;
    }
    if (t == 0) g_thr[row] = lo;
}

// ---------------- y = sparse(z) . ow, with the source's un-mix ---------------
// grid (S, B), block 256. y[b,s,h*64+d] = sum_h2 zs[b*16+h, h2, s] * ow[h2,d]
__global__ __launch_bounds__(256) void y_kernel() {
    __shared__ float zs[16][17];
    __shared__ float ows[NH * HD];
    int t = threadIdx.x;
    int s = blockIdx.x, b = blockIdx.y;
    for (int i = t; i < NH * HD; i += 256) ows[i] = g_ow[i];
    {
        int h = t >> 4, h2 = t & 15;
        int n = b * 16 + h;
        float zv = g_z[((size_t)n * 16 + h2) * Sx + s];
        zs[h][h2] = (f2ord(zv) >= g_thr[n * 16 + h2]) ? zv : 0.f;
    }
    __syncthreads();
#pragma unroll
    for (int k2 = 0; k2 < 4; k2++) {
        int dg = t + k2 * 256;
        int h = dg >> 6, d = dg & 63;
        float a = 0.f;
#pragma unroll
        for (int h2 = 0; h2 < 16; h2++) a += zs[h][h2] * ows[h2 * HD + d];
        g_y[((size_t)(b * Sx + s)) * Hx + dg] = a;
    }
}

// ---------------- reduce sparse weight means ---------------------------------
__global__ void prep_kernel(const float* __restrict__ swv,
                            const float* __restrict__ swo) {
    int t = threadIdx.x;               // 1024 threads: (h,d)
    int h = t >> 6, d = t & 63;
    float s1 = 0.f, s2 = 0.f;
#pragma unroll 4
    for (int k = 0; k < 128; k++) {
        s1 += swv[((size_t)(h * 64 + d)) * 128 + k];
        s2 += swo[((size_t)(h * 128 + k)) * 64 + d];
    }
    g_vw[t] = s1 * (1.f / 128.f);
    g_ow[t] = s2 * (1.f / 128.f);
}

// ---------------- launch ----------------------------------------------------
extern "C" void kernel_launch(void* const* d_in, const int* in_sizes, int n_in,
                              void* d_out, int out_size) {
    const float* x   = (const float*)d_in[0];
    const float* WQ  = (const float*)d_in[1];
    const float* WK  = (const float*)d_in[2];
    const float* WV  = (const float*)d_in[3];
    const float* WO  = (const float*)d_in[4];
    const float* qw  = (const float*)d_in[5];
    const float* qb  = (const float*)d_in[6];
    const float* kw  = (const float*)d_in[7];
    const float* kb  = (const float*)d_in[8];
    const float* swv = (const float*)d_in[9];
    const float* swo = (const float*)d_in[10];
    float* out = (float*)d_out;

    float *pQ, *pK, *pV, *pY;
    cudaGetSymbolAddress((void**)&pQ, g_Q);
    cudaGetSymbolAddress((void**)&pK, g_K);
    cudaGetSymbolAddress((void**)&pV, g_V);
    cudaGetSymbolAddress((void**)&pY, g_y);

    prep_kernel<<<1, 1024>>>(swv, swo);

    dim3 gg(Hx / BN, BSx / BM);                  // (8, 32)
    sgemm_nt<<<gg, 256>>>(x, WQ, pQ, BSx, Hx, Hx);
    sgemm_nt<<<gg, 256>>>(x, WK, pK, BSx, Hx, Hx);
    sgemm_nt<<<gg, 256>>>(x, WV, pV, BSx, Hx, Hx);

    // 131072 head-rows (Q then K), one warp each, 8 warps per block -> 16384 blocks
    ln_kernel<<<16384, 256>>>(pQ, pK, qw, qb, kw, kb);

    attn_kernel<<<dim3(Sx / 64, NH, Bx), 256>>>(pQ, pK, pV);

    z_kernel<<<dim3(Sx / 128, 32), 256>>>();
    topk_kernel<<<512, 256>>>();
    y_kernel<<<dim3(Sx, Bx), 256>>>();

    sgemm_nt<<<gg, 256>>>(pY, WO, out, BSx, Hx, Hx);
}

// round 3
// speedup vs baseline: 1.0270x; 1.0270x over previous
#include <cuda_runtime.h>
#include <cstdint>
#include <cstddef>

// ---------------- problem constants ----------------
#define Bx 2
#define Sx 2048
#define Hx 1024
#define NH 16
#define HD 64
#define BSx (Bx*Sx)          // 4096
#define TOPK 128
#define LN_EPS 1e-5f

typedef unsigned long long u64;

// ---------------- packed f32x2 helpers (Blackwell FFMA2) ----------------
__device__ __forceinline__ u64 pack2(float x, float y) {
    u64 r; asm("mov.b64 %0,{%1,%2};" : "=l"(r) : "f"(x), "f"(y)); return r;
}
__device__ __forceinline__ u64 dup2(float x) { return pack2(x, x); }
__device__ __forceinline__ void unpk2(u64 v, float& x, float& y) {
    asm("mov.b64 {%0,%1},%2;" : "=f"(x), "=f"(y) : "l"(v));
}
__device__ __forceinline__ void fma2(u64& d, u64 a, u64 b) {
    asm("fma.rn.f32x2 %0,%1,%2,%0;" : "+l"(d) : "l"(a), "l"(b));
}
__device__ __forceinline__ void mul2(u64& d, u64 a) {
    asm("mul.rn.f32x2 %0,%0,%1;" : "+l"(d) : "l"(a));
}

// ---------------- scratch (device globals; no allocation) ----------------
__device__ float    g_Q[BSx*Hx];
__device__ float    g_K[BSx*Hx];
__device__ float    g_V[BSx*Hx];
__device__ float    g_ctx[BSx*Hx];
__device__ float    g_z[32*16*2048];
__device__ unsigned g_thr[32*16];
__device__ float    g_y[BSx*Hx];
__device__ float    g_vw[NH*HD];
__device__ float    g_ow[NH*HD];

__device__ __forceinline__ unsigned f2ord(float f) {
    unsigned u = __float_as_uint(f);
    return (u >> 31) ? ~u : (u | 0x80000000u);
}

// ---------------- SGEMM (NT) with packed f32x2, double-buffered -----------
// C[M,N] = A[M,K] * B[N,K]^T. 128x128 tile, BK=16, 256 threads, 8x8/thread.
#define BM 128
#define BN 128
#define BK 16

__global__ __launch_bounds__(256) void sgemm_nt(const float* __restrict__ A,
                                                const float* __restrict__ B,
                                                float* __restrict__ C,
                                                int M, int N, int K) {
    __shared__ float As[2][BK][BM + 4];   // k-major
    __shared__ float Bs[2][BK][BN + 4];   // k-major
    const int tid = threadIdx.x;
    const int tx = tid & 15, ty = tid >> 4;
    const int m0 = blockIdx.y * BM, n0 = blockIdx.x * BN;

    u64 acc[8][4];
#pragma unroll
    for (int i = 0; i < 8; i++)
#pragma unroll
        for (int j = 0; j < 4; j++) acc[i][j] = 0ull;

    int arow[2], ac4[2];
#pragma unroll
    for (int it = 0; it < 2; it++) {
        int idx = tid + it * 256;
        arow[it] = idx >> 2;
        ac4[it]  = (idx & 3) * 4;
    }

    float4 pa[2], pb[2];
#pragma unroll
    for (int it = 0; it < 2; it++) {
        pa[it] = *(const float4*)(A + (size_t)(m0 + arow[it]) * K + ac4[it]);
        pb[it] = *(const float4*)(B + (size_t)(n0 + arow[it]) * K + ac4[it]);
    }

    const int nk = K / BK;
    int buf = 0;
    for (int t = 0; t < nk; t++) {
        // store prefetched tile into smem[buf] (k-major)
#pragma unroll
        for (int it = 0; it < 2; it++) {
            As[buf][ac4[it] + 0][arow[it]] = pa[it].x;
            As[buf][ac4[it] + 1][arow[it]] = pa[it].y;
            As[buf][ac4[it] + 2][arow[it]] = pa[it].z;
            As[buf][ac4[it] + 3][arow[it]] = pa[it].w;
            Bs[buf][ac4[it] + 0][arow[it]] = pb[it].x;
            Bs[buf][ac4[it] + 1][arow[it]] = pb[it].y;
            Bs[buf][ac4[it] + 2][arow[it]] = pb[it].z;
            Bs[buf][ac4[it] + 3][arow[it]] = pb[it].w;
        }
        __syncthreads();
        if (t + 1 < nk) {
            int k0 = (t + 1) * BK;
#pragma unroll
            for (int it = 0; it < 2; it++) {
                pa[it] = *(const float4*)(A + (size_t)(m0 + arow[it]) * K + k0 + ac4[it]);
                pb[it] = *(const float4*)(B + (size_t)(n0 + arow[it]) * K + k0 + ac4[it]);
            }
        }
#pragma unroll
        for (int kk = 0; kk < BK; kk++) {
            float4 a0 = *(const float4*)&As[buf][kk][ty * 8];
            float4 a1 = *(const float4*)&As[buf][kk][ty * 8 + 4];
            ulonglong2 b01 = *(const ulonglong2*)&Bs[buf][kk][tx * 8];
            ulonglong2 b23 = *(const ulonglong2*)&Bs[buf][kk][tx * 8 + 4];
            float av[8] = {a0.x, a0.y, a0.z, a0.w, a1.x, a1.y, a1.z, a1.w};
#pragma unroll
            for (int i = 0; i < 8; i++) {
                u64 ad = dup2(av[i]);
                fma2(acc[i][0], ad, b01.x);
                fma2(acc[i][1], ad, b01.y);
                fma2(acc[i][2], ad, b23.x);
                fma2(acc[i][3], ad, b23.y);
            }
        }
        buf ^= 1;
    }
#pragma unroll
    for (int i = 0; i < 8; i++) {
        size_t off = (size_t)(m0 + ty * 8 + i) * N + n0 + tx * 8;
        ulonglong2 s0 = {acc[i][0], acc[i][1]};
        ulonglong2 s1 = {acc[i][2], acc[i][3]};
        *(ulonglong2*)(C + off)     = s0;
        *(ulonglong2*)(C + off + 4) = s1;
    }
}

// ---------------- per-head LayerNorm on Q and K (in place) ------------------
__global__ __launch_bounds__(256) void ln_kernel(float* __restrict__ Q,
                                                 float* __restrict__ Kp,
                                                 const float* __restrict__ qw,
                                                 const float* __restrict__ qb,
                                                 const float* __restrict__ kw,
                                                 const float* __restrict__ kb) {
    int warp = threadIdx.x >> 5, lane = threadIdx.x & 31;
    int rid = blockIdx.x * 8 + warp;
    float* base;
    const float *w, *bb;
    if (rid < BSx * NH) { base = Q + (size_t)rid * 64; w = qw; bb = qb; }
    else { base = Kp + (size_t)(rid - BSx * NH) * 64; w = kw; bb = kb; }
    float x0 = base[lane], x1 = base[lane + 32];
    float sum = x0 + x1;
#pragma unroll
    for (int off = 16; off; off >>= 1) sum += __shfl_xor_sync(~0u, sum, off);
    float mu = sum * (1.f / 64.f);
    float d0 = x0 - mu, d1 = x1 - mu;
    float vs = d0 * d0 + d1 * d1;
#pragma unroll
    for (int off = 16; off; off >>= 1) vs += __shfl_xor_sync(~0u, vs, off);
    float rs = rsqrtf(vs * (1.f / 64.f) + LN_EPS);
    base[lane]      = d0 * rs * w[lane]      + bb[lane];
    base[lane + 32] = d1 * rs * w[lane + 32] + bb[lane + 32];
}

// ---------------- flash attention, fp32 + f32x2 ------------------------------
// grid (S/128, nh, B), block 256 (ty=tid>>4 owns 8 q-rows, tx owns 2 score
// cols / 4 ctx cols). Q tile 128, K tile 32. Dynamic smem, k-major Q/K.
#define QT 128
#define KT 32
#define QS_ST 132
#define KS_ST 36
#define VS_ST 68
#define PS_ST 132
#define OFF_KS (64*QS_ST)
#define OFF_VS (OFF_KS + 64*KS_ST)
#define OFF_PS (OFF_VS + KT*VS_ST)
#define ATTN_SMEM ((OFF_PS + KT*PS_ST) * 4)

__global__ __launch_bounds__(256) void attn_kernel(const float* __restrict__ Qg,
                                                   const float* __restrict__ Kg,
                                                   const float* __restrict__ Vg) {
    extern __shared__ float sm[];
    float* Qs = sm;              // [k=64][m=128+4]
    float* Ks = sm + OFF_KS;     // [k=64][j=32+4]
    float* Vs = sm + OFF_VS;     // [c=32][d=64+4]
    float* Ps = sm + OFF_PS;     // [c=32][m=128+4]

    const int qt = blockIdx.x, h = blockIdx.y, b = blockIdx.z;
    const int tid = threadIdx.x;
    const int tx = tid & 15, ty = tid >> 4;
    const int q0 = qt * QT;
    const float scale = 0.125f;

    const float* qp = Qg + (size_t)(b * Sx + q0) * Hx + h * HD;
#pragma unroll
    for (int it = 0; it < 8; it++) {
        int idx = tid + it * 256;          // 128 rows x 16 float4
        int r = idx >> 4, c4 = (idx & 15) * 4;
        float4 v = *(const float4*)(qp + (size_t)r * Hx + c4);
        Qs[(c4 + 0) * QS_ST + r] = v.x * scale;
        Qs[(c4 + 1) * QS_ST + r] = v.y * scale;
        Qs[(c4 + 2) * QS_ST + r] = v.z * scale;
        Qs[(c4 + 3) * QS_ST + r] = v.w * scale;
    }

    u64 acc[8][2];
    float m_run[8], l_run[8];
#pragma unroll
    for (int i = 0; i < 8; i++) {
        acc[i][0] = 0ull; acc[i][1] = 0ull;
        m_run[i] = -1e30f; l_run[i] = 0.f;
    }

    for (int kt = 0; kt < Sx / KT; kt++) {
        __syncthreads();
        const float* kp = Kg + (size_t)(b * Sx + kt * KT) * Hx + h * HD;
        const float* vp = Vg + (size_t)(b * Sx + kt * KT) * Hx + h * HD;
#pragma unroll
        for (int it = 0; it < 2; it++) {
            int idx = tid + it * 256;      // 32 rows x 16 float4
            int r = idx >> 4, c4 = (idx & 15) * 4;
            float4 kv = *(const float4*)(kp + (size_t)r * Hx + c4);
            Ks[(c4 + 0) * KS_ST + r] = kv.x;
            Ks[(c4 + 1) * KS_ST + r] = kv.y;
            Ks[(c4 + 2) * KS_ST + r] = kv.z;
            Ks[(c4 + 3) * KS_ST + r] = kv.w;
            float4 vv = *(const float4*)(vp + (size_t)r * Hx + c4);
            *(float4*)&Vs[r * VS_ST + c4] = vv;
        }
        __syncthreads();

        // GEMM1: pairs along query rows (i). s2[ip][j] holds rows 2ip,2ip+1.
        u64 s2[4][2];
#pragma unroll
        for (int ip = 0; ip < 4; ip++) { s2[ip][0] = 0ull; s2[ip][1] = 0ull; }
#pragma unroll 16
        for (int kk = 0; kk < 64; kk++) {
            ulonglong2 a01 = *(const ulonglong2*)&Qs[kk * QS_ST + ty * 8];
            ulonglong2 a23 = *(const ulonglong2*)&Qs[kk * QS_ST + ty * 8 + 4];
            float2 bv = *(const float2*)&Ks[kk * KS_ST + tx * 2];
            u64 bd0 = dup2(bv.x), bd1 = dup2(bv.y);
            fma2(s2[0][0], a01.x, bd0); fma2(s2[0][1], a01.x, bd1);
            fma2(s2[1][0], a01.y, bd0); fma2(s2[1][1], a01.y, bd1);
            fma2(s2[2][0], a23.x, bd0); fma2(s2[2][1], a23.x, bd1);
            fma2(s2[3][0], a23.y, bd0); fma2(s2[3][1], a23.y, bd1);
        }
        float s[8][2];
#pragma unroll
        for (int ip = 0; ip < 4; ip++) {
            unpk2(s2[ip][0], s[2 * ip][0], s[2 * ip + 1][0]);
            unpk2(s2[ip][1], s[2 * ip][1], s[2 * ip + 1][1]);
        }
        // online softmax per row (reduce across the 16-lane tx group)
#pragma unroll
        for (int i = 0; i < 8; i++) {
            float tmax = fmaxf(s[i][0], s[i][1]);
#pragma unroll
            for (int off = 8; off; off >>= 1)
                tmax = fmaxf(tmax, __shfl_xor_sync(~0u, tmax, off, 16));
            float mnew = fmaxf(m_run[i], tmax);
            float p0 = __expf(s[i][0] - mnew);
            float p1 = __expf(s[i][1] - mnew);
            float lsum = p0 + p1;
#pragma unroll
            for (int off = 8; off; off >>= 1)
                lsum += __shfl_xor_sync(~0u, lsum, off, 16);
            float alpha = __expf(m_run[i] - mnew);
            l_run[i] = l_run[i] * alpha + lsum;
            m_run[i] = mnew;
            u64 ad = dup2(alpha);
            mul2(acc[i][0], ad); mul2(acc[i][1], ad);
            Ps[(tx * 2 + 0) * PS_ST + ty * 8 + i] = p0;
            Ps[(tx * 2 + 1) * PS_ST + ty * 8 + i] = p1;
        }
        __syncthreads();

        // GEMM2: pairs along ctx cols (j). acc[i][jp], jp covers d=tx*4+2jp..+1
#pragma unroll 8
        for (int c = 0; c < KT; c++) {
            ulonglong2 bv = *(const ulonglong2*)&Vs[c * VS_ST + tx * 4];
            float4 pA = *(const float4*)&Ps[c * PS_ST + ty * 8];
            float4 pB = *(const float4*)&Ps[c * PS_ST + ty * 8 + 4];
            float pv[8] = {pA.x, pA.y, pA.z, pA.w, pB.x, pB.y, pB.z, pB.w};
#pragma unroll
            for (int i = 0; i < 8; i++) {
                u64 pd = dup2(pv[i]);
                fma2(acc[i][0], pd, bv.x);
                fma2(acc[i][1], pd, bv.y);
            }
        }
    }

    float* ob = g_ctx + ((size_t)(b * NH + h) * Sx + q0) * HD;
#pragma unroll
    for (int i = 0; i < 8; i++) {
        u64 iv = dup2(1.f / l_run[i]);
        u64 o0 = acc[i][0], o1 = acc[i][1];
        mul2(o0, iv); mul2(o1, iv);
        ulonglong2 st = {o0, o1};
        *(ulonglong2*)(ob + (size_t)(ty * 8 + i) * HD + tx * 4) = st;
    }
}

// ---------------- z = mixed-context . vw  ------------------------------------
__global__ __launch_bounds__(256) void z_kernel() {
    __shared__ float cs[128][65];
    __shared__ float vws[NH * HD];
    int t = threadIdx.x;
    int n = blockIdx.y, m0 = blockIdx.x * 128;
    for (int i = t; i < NH * HD; i += 256) vws[i] = g_vw[i];
    int b = n >> 4, hi = n & 15;
#pragma unroll 8
    for (int it = 0; it < 32; it++) {
        int f = t + it * 256;
        int j = f >> 6, d = f & 63;
        int m = m0 + j;
        int t2 = hi * Sx + m;
        int s = t2 >> 4, hh = t2 & 15;
        cs[j][d] = g_ctx[((size_t)(b * NH + hh) * Sx + s) * HD + d];
    }
    __syncthreads();
#pragma unroll 1
    for (int p = 0; p < 8; p++) {
        int h2 = p * 2 + (t >> 7);
        int ml = t & 127;
        const float* vr = &vws[h2 * HD];
        float a = 0.f;
#pragma unroll
        for (int d = 0; d < 64; d++) a += cs[ml][d] * vr[d];
        g_z[((size_t)n * 16 + h2) * Sx + m0 + ml] = a;
    }
}

// ---------------- top-128 threshold per row ----------------------------------
__global__ __launch_bounds__(256) void topk_kernel() {
    int row = blockIdx.x, t = threadIdx.x;
    const float* zr = g_z + (size_t)row * Sx;
    unsigned v[8];
#pragma unroll
    for (int i = 0; i < 8; i++) v[i] = f2ord(zr[t + i * 256]);
    __shared__ int scnt;
    unsigned lo = 0u, hi = 0xFFFFFFFFu;
    while (lo < hi) {
        unsigned mid = lo + ((hi - lo) >> 1);
        int c = 0;
#pragma unroll
        for (int i = 0; i < 8; i++) c += (v[i] > mid);
#pragma unroll
        for (int off = 16; off; off >>= 1) c += __shfl_xor_sync(~0u, c, off);
        __syncthreads();
        if (t == 0) scnt = 0;
        __syncthreads();
        if ((t & 31) == 0) atomicAdd(&scnt, c);
        __syncthreads();
        int tot = scnt;
        if (tot >= TOPK) lo = mid + 1; else hi = mid;
    }
    if (t == 0) g_thr[row] = lo;
}

// ---------------- y = sparse(z) . ow -----------------------------------------
__global__ __launch_bounds__(256) void y_kernel() {
    __shared__ float zs[16][17];
    __shared__ float ows[NH * HD];
    int t = threadIdx.x;
    int s = blockIdx.x, b = blockIdx.y;
    for (int i = t; i < NH * HD; i += 256) ows[i] = g_ow[i];
    {
        int h = t >> 4, h2 = t & 15;
        int n = b * 16 + h;
        float zv = g_z[((size_t)n * 16 + h2) * Sx + s];
        zs[h][h2] = (f2ord(zv) >= g_thr[n * 16 + h2]) ? zv : 0.f;
    }
    __syncthreads();
#pragma unroll
    for (int k2 = 0; k2 < 4; k2++) {
        int dg = t + k2 * 256;
        int h = dg >> 6, d = dg & 63;
        float a = 0.f;
#pragma unroll
        for (int h2 = 0; h2 < 16; h2++) a += zs[h][h2] * ows[h2 * HD + d];
        g_y[((size_t)(b * Sx + s)) * Hx + dg] = a;
    }
}

// ---------------- reduce sparse weight means ---------------------------------
__global__ void prep_kernel(const float* __restrict__ swv,
                            const float* __restrict__ swo) {
    int t = threadIdx.x;
    int h = t >> 6, d = t & 63;
    float s1 = 0.f, s2 = 0.f;
#pragma unroll 4
    for (int k = 0; k < 128; k++) {
        s1 += swv[((size_t)(h * 64 + d)) * 128 + k];
        s2 += swo[((size_t)(h * 128 + k)) * 64 + d];
    }
    g_vw[t] = s1 * (1.f / 128.f);
    g_ow[t] = s2 * (1.f / 128.f);
}

// ---------------- launch ----------------------------------------------------
extern "C" void kernel_launch(void* const* d_in, const int* in_sizes, int n_in,
                              void* d_out, int out_size) {
    const float* x   = (const float*)d_in[0];
    const float* WQ  = (const float*)d_in[1];
    const float* WK  = (const float*)d_in[2];
    const float* WV  = (const float*)d_in[3];
    const float* WO  = (const float*)d_in[4];
    const float* qw  = (const float*)d_in[5];
    const float* qb  = (const float*)d_in[6];
    const float* kw  = (const float*)d_in[7];
    const float* kb  = (const float*)d_in[8];
    const float* swv = (const float*)d_in[9];
    const float* swo = (const float*)d_in[10];
    float* out = (float*)d_out;

    float *pQ, *pK, *pV, *pY;
    cudaGetSymbolAddress((void**)&pQ, g_Q);
    cudaGetSymbolAddress((void**)&pK, g_K);
    cudaGetSymbolAddress((void**)&pV, g_V);
    cudaGetSymbolAddress((void**)&pY, g_y);

    static int attr_done = 0;
    if (!attr_done) {
        cudaFuncSetAttribute(attn_kernel,
                             cudaFuncAttributeMaxDynamicSharedMemorySize,
                             ATTN_SMEM);
        attr_done = 1;
    }

    prep_kernel<<<1, 1024>>>(swv, swo);

    dim3 gg(Hx / BN, BSx / BM);                  // (8, 32)
    sgemm_nt<<<gg, 256>>>(x, WQ, pQ, BSx, Hx, Hx);
    sgemm_nt<<<gg, 256>>>(x, WK, pK, BSx, Hx, Hx);
    sgemm_nt<<<gg, 256>>>(x, WV, pV, BSx, Hx, Hx);

    ln_kernel<<<16384, 256>>>(pQ, pK, qw, qb, kw, kb);

    attn_kernel<<<dim3(Sx / QT, NH, Bx), 256, ATTN_SMEM>>>(pQ, pK, pV);

    z_kernel<<<dim3(Sx / 128, 32), 256>>>();
    topk_kernel<<<512, 256>>>();
    y_kernel<<<dim3(Sx, Bx), 256>>>();

    sgemm_nt<<<gg, 256>>>(pY, WO, out, BSx, Hx, Hx);
}